// round 6
// baseline (speedup 1.0000x reference)
#include <cuda_runtime.h>
#include <cuda_bf16.h>
#include <cstdint>

#define ROWSTRIDE 5248
#define NTILES    1312
#define GRIDSZ    148
#define SMEM_BYTES 131072

#define BUFSTR 65536u
#define O_ALO  16384u
#define O_BHI  32768u
#define O_BLO  49152u

static __device__ __forceinline__ uint32_t smem_u32(const void* p) {
    uint32_t a;
    asm("{ .reg .u64 t; cvta.to.shared.u64 t, %1; cvt.u32.u64 %0, t; }"
        : "=r"(a) : "l"(p));
    return a;
}
static __device__ __forceinline__ void ldsm4(uint32_t* r, uint32_t a) {
    asm volatile("ldmatrix.sync.aligned.m8n8.x4.shared.b16 {%0,%1,%2,%3}, [%4];"
                 : "=r"(r[0]), "=r"(r[1]), "=r"(r[2]), "=r"(r[3]) : "r"(a));
}
static __device__ __forceinline__ void ldsm4t(uint32_t* r, uint32_t a) {
    asm volatile("ldmatrix.sync.aligned.m8n8.x4.trans.shared.b16 {%0,%1,%2,%3}, [%4];"
                 : "=r"(r[0]), "=r"(r[1]), "=r"(r[2]), "=r"(r[3]) : "r"(a));
}
static __device__ __forceinline__ void mma_bf16(float* c, const uint32_t* a, const uint32_t* b) {
    asm volatile("mma.sync.aligned.m16n8k16.row.col.f32.bf16.bf16.f32 "
                 "{%0,%1,%2,%3}, {%4,%5,%6,%7}, {%8,%9}, {%0,%1,%2,%3};"
                 : "+f"(c[0]), "+f"(c[1]), "+f"(c[2]), "+f"(c[3])
                 : "r"(a[0]), "r"(a[1]), "r"(a[2]), "r"(a[3]), "r"(b[0]), "r"(b[1]));
}
static __device__ __forceinline__ uint32_t hi2(float a, float b, float& ra, float& rb) {
    __nv_bfloat16 ha = __float2bfloat16(a), hb = __float2bfloat16(b);
    ra = a - __bfloat162float(ha);
    rb = b - __bfloat162float(hb);
    return (uint32_t)__bfloat16_as_ushort(ha) | ((uint32_t)__bfloat16_as_ushort(hb) << 16);
}
static __device__ __forceinline__ uint32_t lo2(float a, float b) {
    return (uint32_t)__bfloat16_as_ushort(__float2bfloat16(a)) |
           ((uint32_t)__bfloat16_as_ushort(__float2bfloat16(b)) << 16);
}

__global__ void __launch_bounds__(256, 1)
poslin_kernel(const float* __restrict__ x, const float* __restrict__ W,
              const float* __restrict__ bias, float* __restrict__ out)
{
    extern __shared__ __align__(128) char smem[];
    const uint32_t sb = smem_u32(smem);
    const int tid  = threadIdx.x;
    const int lane = tid & 31;
    const int wid  = tid >> 5;
    const int m0 = (wid & 3) << 5;     // warp M offset (batch rows)
    const int n0 = (wid >> 2) << 6;    // warp N offset (filters)
    const int g8 = lane >> 2, tig = lane & 3;

    // ldmatrix lane-address components
    const uint32_t aRowB = (uint32_t)(m0 + (lane & 15));         // + 16*i
    const uint32_t aKC   = (uint32_t)(lane >> 4);                // 0/1
    const uint32_t l7    = (uint32_t)(lane & 7);
    const uint32_t bKrB  = (uint32_t)(lane & 15);                // + 16*ks
    const uint32_t bNCB  = (uint32_t)((n0 >> 3) + (lane >> 4));  // + 2*jj

    // convert/store lane constants
    const int xq = tid & 15, xr0 = tid >> 4;      // x: q = float4-in-row, row base
    const int wq = tid & 31, wk0 = tid >> 5;      // W: q = float4-in-row, k base
    const uint32_t xCvt = ((((uint32_t)(xq >> 1)) ^ ((uint32_t)xr0 & 7u)) << 4)
                        + (uint32_t)((xq & 1) << 3);
    const uint32_t wCvt = ((((uint32_t)(wq >> 1)) ^ ((uint32_t)wk0 & 7u)) << 4)
                        + (uint32_t)((wq & 1) << 3);

    const int start = (int)(((long)blockIdx.x * NTILES) / GRIDSZ);
    const int end   = (int)(((long)(blockIdx.x + 1) * NTILES) / GRIDSZ);

    for (int t = start; t < end; ++t) {
        const int s = t >> 5, mt = t & 31, bbase = mt << 7;
        const int ebase0 = (s - 1) * 128;
        const float* Ws = W + (size_t)s * (384 * 128);

        float acc[2][8][4];
        _Pragma("unroll")
        for (int i = 0; i < 2; ++i)
            _Pragma("unroll")
            for (int j = 0; j < 8; ++j)
                _Pragma("unroll")
                for (int u = 0; u < 4; ++u) acc[i][j][u] = 0.f;

        float4 xr[8], wr[8];

#define LOADC(cc) do {                                                          \
    const int e_ = ebase0 + (cc) * 64 + xq * 4;                                 \
    const bool v_ = (e_ >= 0) && (e_ < ROWSTRIDE);                              \
    _Pragma("unroll")                                                           \
    for (int it = 0; it < 8; ++it)                                              \
        xr[it] = v_ ? *(const float4*)(x + (size_t)(bbase + xr0 + 16*it) * ROWSTRIDE + e_) \
                    : make_float4(0.f, 0.f, 0.f, 0.f);                          \
    _Pragma("unroll")                                                           \
    for (int it = 0; it < 8; ++it)                                              \
        wr[it] = *(const float4*)(Ws + (size_t)((cc) * 64 + wk0 + 8*it) * 128 + wq * 4); \
} while (0)

#define CVTC(bf) do {                                                           \
    _Pragma("unroll")                                                           \
    for (int it = 0; it < 8; ++it) {                                            \
        float r0_, r1_, r2_, r3_;                                               \
        uint32_t h0_ = hi2(xr[it].x, xr[it].y, r0_, r1_);                       \
        uint32_t h1_ = hi2(xr[it].z, xr[it].w, r2_, r3_);                       \
        uint32_t o_ = (uint32_t)(bf) * BUFSTR + (uint32_t)(xr0 + 16*it) * 128u + xCvt; \
        *(uint2*)(smem + o_)         = make_uint2(h0_, h1_);                    \
        *(uint2*)(smem + o_ + O_ALO) = make_uint2(lo2(r0_, r1_), lo2(r2_, r3_));\
    }                                                                           \
    _Pragma("unroll")                                                           \
    for (int it = 0; it < 8; ++it) {                                            \
        float r0_, r1_, r2_, r3_;                                               \
        uint32_t h0_ = hi2(wr[it].x, wr[it].y, r0_, r1_);                       \
        uint32_t h1_ = hi2(wr[it].z, wr[it].w, r2_, r3_);                       \
        uint32_t o_ = (uint32_t)(bf) * BUFSTR + O_BHI + (uint32_t)(wk0 + 8*it) * 256u + wCvt; \
        *(uint2*)(smem + o_)                   = make_uint2(h0_, h1_);          \
        *(uint2*)(smem + o_ + (O_BLO - O_BHI)) = make_uint2(lo2(r0_, r1_), lo2(r2_, r3_)); \
    }                                                                           \
} while (0)

#define MMAC(bf) do {                                                           \
    const uint32_t Ab = sb + (uint32_t)(bf) * BUFSTR;                           \
    _Pragma("unroll")                                                           \
    for (int ks = 0; ks < 4; ++ks) {                                            \
        uint32_t ah[2][4], al[2][4];                                            \
        _Pragma("unroll")                                                       \
        for (int i = 0; i < 2; ++i) {                                           \
            uint32_t ad = Ab + (aRowB + 16u*i) * 128u                           \
                        + ((((uint32_t)(ks * 2) + aKC) ^ l7) << 4);             \
            ldsm4(ah[i], ad);                                                   \
            ldsm4(al[i], ad + O_ALO);                                           \
        }                                                                       \
        _Pragma("unroll")                                                       \
        for (int jj = 0; jj < 4; ++jj) {                                        \
            uint32_t bd = Ab + O_BHI + (bKrB + 16u*ks) * 256u                   \
                        + (((bNCB + 2u*jj) ^ l7) << 4);                         \
            uint32_t bfr[4];                                                    \
            ldsm4t(bfr, bd);                                                    \
            _Pragma("unroll")                                                   \
            for (int i = 0; i < 2; ++i) {                                       \
                mma_bf16(acc[i][2*jj],     ah[i], bfr);                         \
                mma_bf16(acc[i][2*jj + 1], ah[i], bfr + 2);                     \
                mma_bf16(acc[i][2*jj],     al[i], bfr);                         \
                mma_bf16(acc[i][2*jj + 1], al[i], bfr + 2);                     \
            }                                                                   \
            ldsm4t(bfr, bd + (O_BLO - O_BHI));                                  \
            _Pragma("unroll")                                                   \
            for (int i = 0; i < 2; ++i) {                                       \
                mma_bf16(acc[i][2*jj],     ah[i], bfr);                         \
                mma_bf16(acc[i][2*jj + 1], ah[i], bfr + 2);                     \
            }                                                                   \
        }                                                                       \
    }                                                                           \
} while (0)

        // prologue: chunk 0
        LOADC(0);
        CVTC(0);
        __syncthreads();

        _Pragma("unroll")
        for (int c = 0; c < 6; ++c) {
            if (c < 5) LOADC(c + 1);      // LDGs in flight during MMA below
            MMAC(c & 1);
            if (c < 5) CVTC((c + 1) & 1);
            __syncthreads();
        }

#undef LOADC
#undef CVTC
#undef MMAC

        // epilogue: bias + relu + store (f-contiguous float2)
        const float* brow = bias + s * 128;
        _Pragma("unroll")
        for (int j = 0; j < 8; ++j) {
            const int n = n0 + 8 * j + 2 * tig;
            const float b0 = brow[n], b1 = brow[n + 1];
            _Pragma("unroll")
            for (int i = 0; i < 2; ++i) {
                const size_t rb = (size_t)(bbase + m0 + 16 * i + g8) * ROWSTRIDE
                                + (size_t)s * 128 + n;
                float2 v0, v1;
                v0.x = fmaxf(acc[i][j][0] + b0, 0.f);
                v0.y = fmaxf(acc[i][j][1] + b1, 0.f);
                v1.x = fmaxf(acc[i][j][2] + b0, 0.f);
                v1.y = fmaxf(acc[i][j][3] + b1, 0.f);
                *(float2*)(out + rb)                 = v0;
                *(float2*)(out + rb + 8 * ROWSTRIDE) = v1;
            }
        }
    }
}

extern "C" void kernel_launch(void* const* d_in, const int* in_sizes, int n_in,
                              void* d_out, int out_size) {
    const float* x = (const float*)d_in[0];
    const float* W = (const float*)d_in[1];
    const float* b = (const float*)d_in[2];
    float* out = (float*)d_out;
    cudaFuncSetAttribute(poslin_kernel,
                         cudaFuncAttributeMaxDynamicSharedMemorySize, SMEM_BYTES);
    poslin_kernel<<<GRIDSZ, 256, SMEM_BYTES>>>(x, W, b, out);
}

// round 7
// speedup vs baseline: 1.0830x; 1.0830x over previous
#include <cuda_runtime.h>
#include <cuda_bf16.h>
#include <cstdint>

#define ROWSTRIDE 5248
#define NTILES    1312
#define GRIDSZ    148
#define NTHREADS  512
#define SMEM_BYTES 131072

#define BUFSTR 65536u
#define O_ALO  16384u
#define O_BHI  32768u
#define O_BLO  49152u

static __device__ __forceinline__ uint32_t smem_u32(const void* p) {
    uint32_t a;
    asm("{ .reg .u64 t; cvta.to.shared.u64 t, %1; cvt.u32.u64 %0, t; }"
        : "=r"(a) : "l"(p));
    return a;
}
static __device__ __forceinline__ void ldsm4(uint32_t* r, uint32_t a) {
    asm volatile("ldmatrix.sync.aligned.m8n8.x4.shared.b16 {%0,%1,%2,%3}, [%4];"
                 : "=r"(r[0]), "=r"(r[1]), "=r"(r[2]), "=r"(r[3]) : "r"(a));
}
static __device__ __forceinline__ void ldsm4t(uint32_t* r, uint32_t a) {
    asm volatile("ldmatrix.sync.aligned.m8n8.x4.trans.shared.b16 {%0,%1,%2,%3}, [%4];"
                 : "=r"(r[0]), "=r"(r[1]), "=r"(r[2]), "=r"(r[3]) : "r"(a));
}
static __device__ __forceinline__ void mma_bf16(float* c, const uint32_t* a, const uint32_t* b) {
    asm volatile("mma.sync.aligned.m16n8k16.row.col.f32.bf16.bf16.f32 "
                 "{%0,%1,%2,%3}, {%4,%5,%6,%7}, {%8,%9}, {%0,%1,%2,%3};"
                 : "+f"(c[0]), "+f"(c[1]), "+f"(c[2]), "+f"(c[3])
                 : "r"(a[0]), "r"(a[1]), "r"(a[2]), "r"(a[3]), "r"(b[0]), "r"(b[1]));
}
static __device__ __forceinline__ uint32_t hi2(float a, float b, float& ra, float& rb) {
    __nv_bfloat16 ha = __float2bfloat16(a), hb = __float2bfloat16(b);
    ra = a - __bfloat162float(ha);
    rb = b - __bfloat162float(hb);
    return (uint32_t)__bfloat16_as_ushort(ha) | ((uint32_t)__bfloat16_as_ushort(hb) << 16);
}
static __device__ __forceinline__ uint32_t lo2(float a, float b) {
    return (uint32_t)__bfloat16_as_ushort(__float2bfloat16(a)) |
           ((uint32_t)__bfloat16_as_ushort(__float2bfloat16(b)) << 16);
}

__global__ void __launch_bounds__(NTHREADS, 1)
poslin_kernel(const float* __restrict__ x, const float* __restrict__ W,
              const float* __restrict__ bias, float* __restrict__ out)
{
    extern __shared__ __align__(128) char smem[];
    const uint32_t sb = smem_u32(smem);
    const int tid  = threadIdx.x;
    const int lane = tid & 31;
    const int wid  = tid >> 5;                 // 0..15
    const int m0 = (wid & 3) << 5;             // warp M offset: 0,32,64,96
    const int n0 = (wid >> 2) << 5;            // warp N offset: 0,32,64,96
    const int g8 = lane >> 2, tig = lane & 3;

    // ldmatrix lane-address components
    const uint32_t aRowB = (uint32_t)(m0 + (lane & 15));         // + 16*i
    const uint32_t aKC   = (uint32_t)(lane >> 4);                // 0/1
    const uint32_t l7    = (uint32_t)(lane & 7);
    const uint32_t bKrB  = (uint32_t)(lane & 15);                // + 16*ks
    const uint32_t bNCB  = (uint32_t)((n0 >> 3) + (lane >> 4));  // + 2*jj

    // load/convert lane constants
    const int xq = tid & 15, xr0 = tid >> 4;   // x: float4-in-row, row base (0..31)
    const int wq = tid & 31, wk0 = tid >> 5;   // W: float4-in-row, k base (0..15)
    const uint32_t xCvt = ((((uint32_t)(xq >> 1)) ^ ((uint32_t)xr0 & 7u)) << 4)
                        + (uint32_t)((xq & 1) << 3);
    const uint32_t wCvt = ((((uint32_t)(wq >> 1)) ^ ((uint32_t)wk0 & 7u)) << 4)
                        + (uint32_t)((wq & 1) << 3);

    const int start = (int)(((long)blockIdx.x * NTILES) / GRIDSZ);
    const int end   = (int)(((long)(blockIdx.x + 1) * NTILES) / GRIDSZ);

    for (int t = start; t < end; ++t) {
        const int s = t >> 5, mt = t & 31, bbase = mt << 7;
        const int ebase0 = (s - 1) * 128;
        const float* Ws = W + (size_t)s * (384 * 128);

        float acc[2][4][4];
        _Pragma("unroll")
        for (int i = 0; i < 2; ++i)
            _Pragma("unroll")
            for (int j = 0; j < 4; ++j)
                _Pragma("unroll")
                for (int u = 0; u < 4; ++u) acc[i][j][u] = 0.f;

        float4 xr[4], wr[4];

#define LOADC(cc) do {                                                          \
    const int e_ = ebase0 + (cc) * 64 + xq * 4;                                 \
    const bool v_ = (e_ >= 0) && (e_ < ROWSTRIDE);                              \
    _Pragma("unroll")                                                           \
    for (int it = 0; it < 4; ++it)                                              \
        xr[it] = v_ ? *(const float4*)(x + (size_t)(bbase + xr0 + 32*it) * ROWSTRIDE + e_) \
                    : make_float4(0.f, 0.f, 0.f, 0.f);                          \
    _Pragma("unroll")                                                           \
    for (int it = 0; it < 4; ++it)                                              \
        wr[it] = *(const float4*)(Ws + (size_t)((cc) * 64 + wk0 + 16*it) * 128 + wq * 4); \
} while (0)

#define CVTC(bf) do {                                                           \
    _Pragma("unroll")                                                           \
    for (int it = 0; it < 4; ++it) {                                            \
        float r0_, r1_, r2_, r3_;                                               \
        uint32_t h0_ = hi2(xr[it].x, xr[it].y, r0_, r1_);                       \
        uint32_t h1_ = hi2(xr[it].z, xr[it].w, r2_, r3_);                       \
        uint32_t o_ = (uint32_t)(bf) * BUFSTR + (uint32_t)(xr0 + 32*it) * 128u + xCvt; \
        *(uint2*)(smem + o_)         = make_uint2(h0_, h1_);                    \
        *(uint2*)(smem + o_ + O_ALO) = make_uint2(lo2(r0_, r1_), lo2(r2_, r3_));\
    }                                                                           \
    _Pragma("unroll")                                                           \
    for (int it = 0; it < 4; ++it) {                                            \
        float r0_, r1_, r2_, r3_;                                               \
        uint32_t h0_ = hi2(wr[it].x, wr[it].y, r0_, r1_);                       \
        uint32_t h1_ = hi2(wr[it].z, wr[it].w, r2_, r3_);                       \
        uint32_t o_ = (uint32_t)(bf) * BUFSTR + O_BHI + (uint32_t)(wk0 + 16*it) * 256u + wCvt; \
        *(uint2*)(smem + o_)           = make_uint2(h0_, h1_);                  \
        *(uint2*)(smem + o_ + 16384u)  = make_uint2(lo2(r0_, r1_), lo2(r2_, r3_)); \
    }                                                                           \
} while (0)

#define MMAC(bf) do {                                                           \
    const uint32_t Ab = sb + (uint32_t)(bf) * BUFSTR;                           \
    _Pragma("unroll")                                                           \
    for (int ks = 0; ks < 4; ++ks) {                                            \
        uint32_t ah[2][4], al[2][4];                                            \
        _Pragma("unroll")                                                       \
        for (int i = 0; i < 2; ++i) {                                           \
            uint32_t ad = Ab + (aRowB + 16u*i) * 128u                           \
                        + ((((uint32_t)(ks * 2) + aKC) ^ l7) << 4);             \
            ldsm4(ah[i], ad);                                                   \
            ldsm4(al[i], ad + O_ALO);                                           \
        }                                                                       \
        _Pragma("unroll")                                                       \
        for (int jj = 0; jj < 2; ++jj) {                                        \
            uint32_t bd = Ab + O_BHI + (bKrB + 16u*ks) * 256u                   \
                        + (((bNCB + 2u*jj) ^ l7) << 4);                         \
            uint32_t bh_[4];                                                    \
            ldsm4t(bh_, bd);                                                    \
            _Pragma("unroll")                                                   \
            for (int i = 0; i < 2; ++i) {                                       \
                mma_bf16(acc[i][2*jj],     ah[i], bh_);                         \
                mma_bf16(acc[i][2*jj + 1], ah[i], bh_ + 2);                     \
                mma_bf16(acc[i][2*jj],     al[i], bh_);                         \
                mma_bf16(acc[i][2*jj + 1], al[i], bh_ + 2);                     \
            }                                                                   \
            uint32_t bl_[4];                                                    \
            ldsm4t(bl_, bd + 16384u);                                           \
            _Pragma("unroll")                                                   \
            for (int i = 0; i < 2; ++i) {                                       \
                mma_bf16(acc[i][2*jj],     ah[i], bl_);                         \
                mma_bf16(acc[i][2*jj + 1], ah[i], bl_ + 2);                     \
            }                                                                   \
        }                                                                       \
    }                                                                           \
} while (0)

        // prologue: chunk 0
        LOADC(0);
        CVTC(0);
        __syncthreads();

        _Pragma("unroll")
        for (int c = 0; c < 6; ++c) {
            if (c < 5) LOADC(c + 1);      // LDGs in flight during MMA below
            MMAC(c & 1);
            if (c < 5) CVTC((c + 1) & 1);
            __syncthreads();
        }

#undef LOADC
#undef CVTC
#undef MMAC

        // epilogue: bias + relu + f-contiguous float2 stores
        const float* brow = bias + s * 128;
        _Pragma("unroll")
        for (int j = 0; j < 4; ++j) {
            const int n = n0 + 8 * j + 2 * tig;
            const float b0 = brow[n], b1 = brow[n + 1];
            _Pragma("unroll")
            for (int i = 0; i < 2; ++i) {
                const size_t rb = (size_t)(bbase + m0 + 16 * i + g8) * ROWSTRIDE
                                + (size_t)s * 128 + n;
                float2 v0, v1;
                v0.x = fmaxf(acc[i][j][0] + b0, 0.f);
                v0.y = fmaxf(acc[i][j][1] + b1, 0.f);
                v1.x = fmaxf(acc[i][j][2] + b0, 0.f);
                v1.y = fmaxf(acc[i][j][3] + b1, 0.f);
                *(float2*)(out + rb)                 = v0;
                *(float2*)(out + rb + 8 * ROWSTRIDE) = v1;
            }
        }
    }
}

extern "C" void kernel_launch(void* const* d_in, const int* in_sizes, int n_in,
                              void* d_out, int out_size) {
    const float* x = (const float*)d_in[0];
    const float* W = (const float*)d_in[1];
    const float* b = (const float*)d_in[2];
    float* out = (float*)d_out;
    cudaFuncSetAttribute(poslin_kernel,
                         cudaFuncAttributeMaxDynamicSharedMemorySize, SMEM_BYTES);
    poslin_kernel<<<GRIDSZ, NTHREADS, SMEM_BYTES>>>(x, W, b, out);
}

// round 8
// speedup vs baseline: 1.2192x; 1.1257x over previous
#include <cuda_runtime.h>
#include <cuda_bf16.h>
#include <cstdint>

#define ROWSTRIDE 5248
#define NTILES    1312
#define GRIDSZ    148
#define NTHREADS  768
#define SMEM_BYTES 131072

#define BUFSTR 65536u
#define O_ALO  16384u
#define O_BHI  32768u

static __device__ __forceinline__ uint32_t smem_u32(const void* p) {
    uint32_t a;
    asm("{ .reg .u64 t; cvta.to.shared.u64 t, %1; cvt.u32.u64 %0, t; }"
        : "=r"(a) : "l"(p));
    return a;
}
static __device__ __forceinline__ void ldsm4(uint32_t* r, uint32_t a) {
    asm volatile("ldmatrix.sync.aligned.m8n8.x4.shared.b16 {%0,%1,%2,%3}, [%4];"
                 : "=r"(r[0]), "=r"(r[1]), "=r"(r[2]), "=r"(r[3]) : "r"(a));
}
static __device__ __forceinline__ void ldsm4t(uint32_t* r, uint32_t a) {
    asm volatile("ldmatrix.sync.aligned.m8n8.x4.trans.shared.b16 {%0,%1,%2,%3}, [%4];"
                 : "=r"(r[0]), "=r"(r[1]), "=r"(r[2]), "=r"(r[3]) : "r"(a));
}
static __device__ __forceinline__ void mma_bf16(float* c, const uint32_t* a, const uint32_t* b) {
    asm volatile("mma.sync.aligned.m16n8k16.row.col.f32.bf16.bf16.f32 "
                 "{%0,%1,%2,%3}, {%4,%5,%6,%7}, {%8,%9}, {%0,%1,%2,%3};"
                 : "+f"(c[0]), "+f"(c[1]), "+f"(c[2]), "+f"(c[3])
                 : "r"(a[0]), "r"(a[1]), "r"(a[2]), "r"(a[3]), "r"(b[0]), "r"(b[1]));
}
static __device__ __forceinline__ uint32_t hi2(float a, float b, float& ra, float& rb) {
    __nv_bfloat16 ha = __float2bfloat16(a), hb = __float2bfloat16(b);
    ra = a - __bfloat162float(ha);
    rb = b - __bfloat162float(hb);
    return (uint32_t)__bfloat16_as_ushort(ha) | ((uint32_t)__bfloat16_as_ushort(hb) << 16);
}
static __device__ __forceinline__ uint32_t lo2(float a, float b) {
    return (uint32_t)__bfloat16_as_ushort(__float2bfloat16(a)) |
           ((uint32_t)__bfloat16_as_ushort(__float2bfloat16(b)) << 16);
}

__global__ void __launch_bounds__(NTHREADS, 1)
poslin_kernel(const float* __restrict__ x, const float* __restrict__ W,
              const float* __restrict__ bias, float* __restrict__ out)
{
    extern __shared__ __align__(128) char smem[];
    const uint32_t sb = smem_u32(smem);
    const int tid  = threadIdx.x;
    const int lane = tid & 31;
    const int wid  = tid >> 5;                 // 0..23

    const int start = (int)(((long)blockIdx.x * NTILES) / GRIDSZ);
    const int end   = (int)(((long)(blockIdx.x + 1) * NTILES) / GRIDSZ);
    const int Ctot  = (end - start) * 6;

    if (wid >= 16) {
        // ================= PRODUCER (8 warps, 256 threads) =================
        const int ptid = tid - 512;
        const int xq = ptid & 15, xr0 = ptid >> 4;   // x: float4-in-row, row base
        const int wq = ptid & 31, wk0 = ptid >> 5;   // W: float4-in-row, k base
        const uint32_t xCvt = ((((uint32_t)(xq >> 1)) ^ ((uint32_t)xr0 & 7u)) << 4)
                            + (uint32_t)((xq & 1) << 3);
        const uint32_t wCvt = ((((uint32_t)(wq >> 1)) ^ ((uint32_t)wk0 & 7u)) << 4)
                            + (uint32_t)((wq & 1) << 3);

        int t = start, c = 0;

#define STSX(v_, row_, bufo_) do {                                              \
    float r0_, r1_, r2_, r3_;                                                   \
    uint32_t h0_ = hi2((v_).x, (v_).y, r0_, r1_);                               \
    uint32_t h1_ = hi2((v_).z, (v_).w, r2_, r3_);                               \
    uint32_t o_ = (bufo_) + (uint32_t)(row_) * 128u + xCvt;                     \
    *(uint2*)(smem + o_)         = make_uint2(h0_, h1_);                        \
    *(uint2*)(smem + o_ + O_ALO) = make_uint2(lo2(r0_, r1_), lo2(r2_, r3_));    \
} while (0)

#define STSW(v_, krow_, bufo_) do {                                             \
    float r0_, r1_, r2_, r3_;                                                   \
    uint32_t h0_ = hi2((v_).x, (v_).y, r0_, r1_);                               \
    uint32_t h1_ = hi2((v_).z, (v_).w, r2_, r3_);                               \
    uint32_t o_ = (bufo_) + O_BHI + (uint32_t)(krow_) * 256u + wCvt;            \
    *(uint2*)(smem + o_)          = make_uint2(h0_, h1_);                       \
    *(uint2*)(smem + o_ + 16384u) = make_uint2(lo2(r0_, r1_), lo2(r2_, r3_));   \
} while (0)

#define FILL(bufv) do {                                                         \
    const int s_ = t >> 5, mt_ = t & 31, bb_ = mt_ << 7;                        \
    const int e_ = (s_ - 1) * 128 + c * 64 + xq * 4;                            \
    const bool v_ = (e_ >= 0) && (e_ < ROWSTRIDE);                              \
    const float* Wc_ = W + (size_t)s_ * (384 * 128) + (size_t)(c * 64) * 128;   \
    const uint32_t bo_ = (uint32_t)(bufv) * BUFSTR;                             \
    float4 xa_[4], wa_[4];                                                      \
    _Pragma("unroll")                                                           \
    for (int it = 0; it < 4; ++it)                                              \
        xa_[it] = v_ ? *(const float4*)(x + (size_t)(bb_ + xr0 + 16*it) * ROWSTRIDE + e_) \
                     : make_float4(0.f, 0.f, 0.f, 0.f);                         \
    _Pragma("unroll")                                                           \
    for (int it = 0; it < 4; ++it)                                              \
        wa_[it] = *(const float4*)(Wc_ + (size_t)(wk0 + 8*it) * 128 + wq * 4);  \
    _Pragma("unroll")                                                           \
    for (int it = 0; it < 4; ++it) STSX(xa_[it], xr0 + 16*it, bo_);             \
    _Pragma("unroll")                                                           \
    for (int it = 0; it < 4; ++it) STSW(wa_[it], wk0 + 8*it, bo_);              \
    _Pragma("unroll")                                                           \
    for (int it = 0; it < 4; ++it)                                              \
        xa_[it] = v_ ? *(const float4*)(x + (size_t)(bb_ + xr0 + 16*(it+4)) * ROWSTRIDE + e_) \
                     : make_float4(0.f, 0.f, 0.f, 0.f);                         \
    _Pragma("unroll")                                                           \
    for (int it = 0; it < 4; ++it)                                              \
        wa_[it] = *(const float4*)(Wc_ + (size_t)(wk0 + 8*(it+4)) * 128 + wq * 4); \
    _Pragma("unroll")                                                           \
    for (int it = 0; it < 4; ++it) STSX(xa_[it], xr0 + 16*(it+4), bo_);         \
    _Pragma("unroll")                                                           \
    for (int it = 0; it < 4; ++it) STSW(wa_[it], wk0 + 8*(it+4), bo_);          \
} while (0)

        FILL(0);                               // chunk 0 before first barrier
        for (int g = 0; g < Ctot; ++g) {
            __syncthreads();
            if (g + 1 < Ctot) {
                if (++c == 6) { c = 0; ++t; }
                FILL((g + 1) & 1);
            }
        }
#undef FILL
#undef STSX
#undef STSW
    } else {
        // ================= CONSUMER (16 warps, 512 threads) =================
        const int m0 = (wid & 3) << 5;
        const int n0 = (wid >> 2) << 5;
        const int g8 = lane >> 2, tig = lane & 3;

        const uint32_t aRowB = (uint32_t)(m0 + (lane & 15));
        const uint32_t aKC   = (uint32_t)(lane >> 4);
        const uint32_t l7    = (uint32_t)(lane & 7);
        const uint32_t bKrB  = (uint32_t)(lane & 15);
        const uint32_t bNCB  = (uint32_t)((n0 >> 3) + (lane >> 4));

        int t = start, c = 0;
        float acc[2][4][4];

        for (int g = 0; g < Ctot; ++g) {
            __syncthreads();
            if (c == 0) {
                _Pragma("unroll")
                for (int i = 0; i < 2; ++i)
                    _Pragma("unroll")
                    for (int j = 0; j < 4; ++j)
                        _Pragma("unroll")
                        for (int u = 0; u < 4; ++u) acc[i][j][u] = 0.f;
            }
            // ---- MMA over buffer g&1 ----
            {
                const uint32_t Ab = sb + (uint32_t)(g & 1) * BUFSTR;
                _Pragma("unroll")
                for (int ks = 0; ks < 4; ++ks) {
                    uint32_t ah[2][4], al[2][4];
                    _Pragma("unroll")
                    for (int i = 0; i < 2; ++i) {
                        uint32_t ad = Ab + (aRowB + 16u*i) * 128u
                                    + ((((uint32_t)(ks * 2) + aKC) ^ l7) << 4);
                        ldsm4(ah[i], ad);
                        ldsm4(al[i], ad + O_ALO);
                    }
                    _Pragma("unroll")
                    for (int jj = 0; jj < 2; ++jj) {
                        uint32_t bd = Ab + O_BHI + (bKrB + 16u*ks) * 256u
                                    + (((bNCB + 2u*jj) ^ l7) << 4);
                        uint32_t bh_[4];
                        ldsm4t(bh_, bd);
                        _Pragma("unroll")
                        for (int i = 0; i < 2; ++i) {
                            mma_bf16(acc[i][2*jj],     ah[i], bh_);
                            mma_bf16(acc[i][2*jj + 1], ah[i], bh_ + 2);
                            mma_bf16(acc[i][2*jj],     al[i], bh_);
                            mma_bf16(acc[i][2*jj + 1], al[i], bh_ + 2);
                        }
                        uint32_t bl_[4];
                        ldsm4t(bl_, bd + 16384u);
                        _Pragma("unroll")
                        for (int i = 0; i < 2; ++i) {
                            mma_bf16(acc[i][2*jj],     ah[i], bl_);
                            mma_bf16(acc[i][2*jj + 1], ah[i], bl_ + 2);
                        }
                    }
                }
            }
            // ---- epilogue at tile end ----
            if (c == 5) {
                const int s = t >> 5, bbase = (t & 31) << 7;
                const float* brow = bias + s * 128;
                _Pragma("unroll")
                for (int j = 0; j < 4; ++j) {
                    const int n = n0 + 8 * j + 2 * tig;
                    const float b0 = brow[n], b1 = brow[n + 1];
                    _Pragma("unroll")
                    for (int i = 0; i < 2; ++i) {
                        const size_t rb = (size_t)(bbase + m0 + 16 * i + g8) * ROWSTRIDE
                                        + (size_t)s * 128 + n;
                        float2 v0, v1;
                        v0.x = fmaxf(acc[i][j][0] + b0, 0.f);
                        v0.y = fmaxf(acc[i][j][1] + b1, 0.f);
                        v1.x = fmaxf(acc[i][j][2] + b0, 0.f);
                        v1.y = fmaxf(acc[i][j][3] + b1, 0.f);
                        *(float2*)(out + rb)                 = v0;
                        *(float2*)(out + rb + 8 * ROWSTRIDE) = v1;
                    }
                }
            }
            if (++c == 6) { c = 0; ++t; }
        }
    }
}

extern "C" void kernel_launch(void* const* d_in, const int* in_sizes, int n_in,
                              void* d_out, int out_size) {
    const float* x = (const float*)d_in[0];
    const float* W = (const float*)d_in[1];
    const float* b = (const float*)d_in[2];
    float* out = (float*)d_out;
    cudaFuncSetAttribute(poslin_kernel,
                         cudaFuncAttributeMaxDynamicSharedMemorySize, SMEM_BYTES);
    poslin_kernel<<<GRIDSZ, NTHREADS, SMEM_BYTES>>>(x, W, b, out);
}